// round 13
// baseline (speedup 1.0000x reference)
#include <cuda_runtime.h>
#include <cuda_fp16.h>

#define Hdim  100
#define Gdim  400
#define T_IN  1000
#define T_TOT 1300
#define NB    4
#define NCTA  128
#define NTHR  800

// Gate-pair packed fp16 weights: [k2][p] -> uint2{ half2(gate p, k=2k2,2k2+1),
//                                                  half2(gate p+200, same k) }
__device__ uint2 g_W1P2[52 * 200];    // W_hh1, zero-padded k2 in {50,51}
__device__ uint2 g_W2P2[100 * 200];   // [W_ih2; W_hh2] over k<200

__global__ void prep_weights(const float* __restrict__ W_hh1,
                             const float* __restrict__ W_ih2,
                             const float* __restrict__ W_hh2) {
    int i = blockIdx.x * blockDim.x + threadIdx.x;
    if (i < 52 * 200) {
        int k2 = i / 200, p = i % 200, k = 2 * k2;
        uint2 u;
        if (k2 < 50) {
            __half2 a = __floats2half2_rn(W_hh1[p*Hdim + k],       W_hh1[p*Hdim + k + 1]);
            __half2 b = __floats2half2_rn(W_hh1[(p+200)*Hdim + k], W_hh1[(p+200)*Hdim + k + 1]);
            u.x = *reinterpret_cast<unsigned*>(&a);
            u.y = *reinterpret_cast<unsigned*>(&b);
        } else { u.x = 0u; u.y = 0u; }
        g_W1P2[i] = u;
    }
    if (i < 100 * 200) {
        int k2 = i / 200, p = i % 200, k = 2 * k2;
        const float* s0 = (k < Hdim) ? (W_ih2 + p*Hdim + k)       : (W_hh2 + p*Hdim + k - Hdim);
        const float* s1 = (k < Hdim) ? (W_ih2 + (p+200)*Hdim + k) : (W_hh2 + (p+200)*Hdim + k - Hdim);
        __half2 a = __floats2half2_rn(s0[0], s0[1]);
        __half2 b = __floats2half2_rn(s1[0], s1[1]);
        uint2 u;
        u.x = *reinterpret_cast<unsigned*>(&a);
        u.y = *reinterpret_cast<unsigned*>(&b);
        g_W2P2[i] = u;
    }
}

typedef unsigned long long u64;
typedef ulonglong2 u64x2;

__device__ __forceinline__ u64 pack2(float v) {
    u64 r; asm("mov.b64 %0, {%1, %1};" : "=l"(r) : "f"(v)); return r;
}
__device__ __forceinline__ void fma2(u64& a, u64 w, u64 h) {
    asm("fma.rn.f32x2 %0, %1, %2, %0;" : "+l"(a) : "l"(w), "l"(h));
}
__device__ __forceinline__ float tanhfast(float x) {
    float y; asm("tanh.approx.f32 %0, %1;" : "=f"(y) : "f"(x)); return y;
}
__device__ __forceinline__ float sigfast(float x) {
    return fmaf(0.5f, tanhfast(0.5f * x), 0.5f);
}

struct L1Const { u64 bb1_0, bb1_1, wi_0, wi_1; };

// L1 gates(x, h1): 13 k-pairs starting k2L1 (zero-padded W). Writes gq1.
__device__ __forceinline__ void l1_gates(const uint2* __restrict__ W1s,
                                         const float4* __restrict__ h1,
                                         u64x2* __restrict__ gq1,
                                         u64x2 xp, const L1Const& C,
                                         int kq, int p, int k2L1) {
    u64 a00 = C.bb1_0, a01 = C.bb1_0, a10 = C.bb1_1, a11 = C.bb1_1;
    if (kq == 0) {
        fma2(a00, C.wi_0, xp.x); fma2(a01, C.wi_0, xp.y);
        fma2(a10, C.wi_1, xp.x); fma2(a11, C.wi_1, xp.y);
    }
    const uint2* wp = W1s + p;
    #pragma unroll 13
    for (int k2 = k2L1; k2 < k2L1 + 13; ++k2) {
        const uint2 wu = wp[k2 * 200];                   // LDS.64
        const float2 wA = __half22float2(*reinterpret_cast<const __half2*>(&wu.x));
        const float2 wB = __half22float2(*reinterpret_cast<const __half2*>(&wu.y));
        const u64x2 h0 = *(const u64x2*)(h1 + 2*k2);     // broadcast (padded zero ok)
        const u64x2 h1v = *(const u64x2*)(h1 + 2*k2 + 1);
        const u64 wA0 = pack2(wA.x), wA1 = pack2(wA.y);
        const u64 wB0 = pack2(wB.x), wB1 = pack2(wB.y);
        fma2(a00, wA0, h0.x); fma2(a01, wA0, h0.y);
        fma2(a00, wA1, h1v.x); fma2(a01, wA1, h1v.y);
        fma2(a10, wB0, h0.x); fma2(a11, wB0, h0.y);
        fma2(a10, wB1, h1v.x); fma2(a11, wB1, h1v.y);
    }
    u64x2 r0; r0.x = a00; r0.y = a01;
    u64x2 r1; r1.x = a10; r1.y = a11;
    gq1[kq * 400 + p]       = r0;
    gq1[kq * 400 + p + 200] = r1;
}

// L2 gates(h1|h2prv): 25 k-pairs; quarters 0-1 read h1, 2-3 read h2prv.
__device__ __forceinline__ void l2_gates(const float4* __restrict__ hb, int l2,
                                         u64x2* __restrict__ gq2,
                                         u64 bb2_0, u64 bb2_1,
                                         int kq, int p, int k2L2) {
    u64 a00 = bb2_0, a01 = bb2_0, a10 = bb2_1, a11 = bb2_1;
    const uint2* wp = g_W2P2 + p;
    #pragma unroll 5
    for (int i = 0; i < 25; ++i) {
        const uint2 wu = __ldg(wp + (k2L2 + i) * 200);   // LDG.64
        const float2 wA = __half22float2(*reinterpret_cast<const __half2*>(&wu.x));
        const float2 wB = __half22float2(*reinterpret_cast<const __half2*>(&wu.y));
        const u64x2 h0 = *(const u64x2*)(hb + 2*(l2 + i));
        const u64x2 h1v = *(const u64x2*)(hb + 2*(l2 + i) + 1);
        const u64 wA0 = pack2(wA.x), wA1 = pack2(wA.y);
        const u64 wB0 = pack2(wB.x), wB1 = pack2(wB.y);
        fma2(a00, wA0, h0.x); fma2(a01, wA0, h0.y);
        fma2(a00, wA1, h1v.x); fma2(a01, wA1, h1v.y);
        fma2(a10, wB0, h0.x); fma2(a11, wB0, h0.y);
        fma2(a10, wB1, h1v.x); fma2(a11, wB1, h1v.y);
    }
    u64x2 r0; r0.x = a00; r0.y = a01;
    u64x2 r1; r1.x = a10; r1.y = a11;
    gq2[kq * 400 + p]       = r0;
    gq2[kq * 400 + p + 200] = r1;
}

// Cell update from 4 quarter partials; writes h[cj] (float4 over batches).
__device__ __forceinline__ void cell_up(const u64x2* __restrict__ gq,
                                        float4* __restrict__ h,
                                        float& c, int cj, int cb) {
    const float* G = (const float*)gq;
    float vi = 0.f, vf = 0.f, vg = 0.f, vo = 0.f;
    #pragma unroll
    for (int q = 0; q < 4; ++q) {
        vi += G[(q*400 +       cj)*4 + cb];
        vf += G[(q*400 + 100 + cj)*4 + cb];
        vg += G[(q*400 + 200 + cj)*4 + cb];
        vo += G[(q*400 + 300 + cj)*4 + cb];
    }
    c = fmaf(sigfast(vf), c, sigfast(vi) * tanhfast(vg));
    ((float*)h)[cj*4 + cb] = sigfast(vo) * tanhfast(c);
}

__device__ __forceinline__ void proj_y(const float4* __restrict__ h2,
                                       const float* __restrict__ wlin, float blin,
                                       float* __restrict__ ysv,
                                       float* __restrict__ out,
                                       int b0, int t, int tid) {
    const int w = tid >> 5, l = tid & 31;
    float s = 0.f;
    #pragma unroll
    for (int j0 = 0; j0 < Hdim; j0 += 32) {
        const int j = j0 + l;
        if (j < Hdim) s = fmaf(((const float*)h2)[j*4 + w], wlin[j], s);
    }
    #pragma unroll
    for (int o = 16; o > 0; o >>= 1) s += __shfl_down_sync(0xffffffffu, s, o);
    if (l == 0) {
        const float y = s + blin;
        out[(b0 + w) * T_TOT + t] = y;
        ysv[w] = y;
    }
}

__global__ __launch_bounds__(NTHR, 1)
void lstm2_kernel(const float* __restrict__ input,
                  const float* __restrict__ W_ih1,
                  const float* __restrict__ b_ih1,
                  const float* __restrict__ b_hh1,
                  const float* __restrict__ b_ih2,
                  const float* __restrict__ b_hh2,
                  const float* __restrict__ W_lin,
                  const float* __restrict__ b_lin,
                  float* __restrict__ out)
{
    extern __shared__ float sm[];
    uint2*  W1s  = (uint2*)sm;                    // [52*200]           (20800 f)
    float4* h1a  = (float4*)(sm + 20800);         // [104] padded       (416 f)
    float4* h1b  = (float4*)(sm + 21216);         // [104]              (416 f)
    float4* h2a  = (float4*)(sm + 21632);         // [100]              (400 f)
    float4* h2b  = (float4*)(sm + 22032);         // [100]              (400 f)
    u64x2*  gq1  = (u64x2*)(sm + 22432);          // [4*400]            (6400 f)
    u64x2*  gq2  = (u64x2*)(sm + 28832);          // [4*400]            (6400 f)
    float4* xin  = (float4*)(sm + 35232);         // [1000]             (4000 f)
    float*  ysv  = sm + 39232;                    // [4]
    float*  wlin = sm + 39236;                    // [100]
    // total 39336 floats = 157344 B

    const int tid = threadIdx.x;
    const int b0  = blockIdx.x * NB;
    const int kq  = tid / 200;       // k-quarter 0..3
    const int p   = tid % 200;       // gate-pair: gates p and p+200
    const int k2L1 = kq * 13;        // L1 k-pair range (padded to 52)
    const int k2L2 = kq * 25;        // L2 global k-pair index
    const int l2   = (kq & 1) * 25;  // local pair index within chosen h buffer

    // ---- one-time init ----
    for (int i = tid; i < 52 * 200 * 2; i += NTHR)
        ((unsigned*)W1s)[i] = ((const unsigned*)g_W1P2)[i];
    for (int i = tid; i < 1632; i += NTHR) sm[20800 + i] = 0.f;   // h buffers+pad
    for (int i = tid; i < NB * T_IN; i += NTHR) {
        int t = i >> 2, b = i & 3;
        ((float*)xin)[i] = input[(b0 + b) * T_IN + t];
    }
    if (tid < Hdim) wlin[tid] = W_lin[tid];
    const float blin_r = __ldg(b_lin);

    L1Const C = {0,0,0,0};
    u64 bb2_0 = 0, bb2_1 = 0;
    if (kq == 0) {
        C.bb1_0 = pack2(b_ih1[p]       + b_hh1[p]);
        C.bb1_1 = pack2(b_ih1[p + 200] + b_hh1[p + 200]);
        C.wi_0  = pack2(W_ih1[p]);
        C.wi_1  = pack2(W_ih1[p + 200]);
        bb2_0   = pack2(b_ih2[p]       + b_hh2[p]);
        bb2_1   = pack2(b_ih2[p + 200] + b_hh2[p + 200]);
    }

    const int cj = tid >> 2;         // cell role (tid < 400)
    const int cb = tid & 3;
    float c1 = 0.f, c2 = 0.f;

    float4 *h1cur = h1a, *h1nxt = h1b, *h2prv = h2a, *h2cur = h2b;
    __syncthreads();

    // ---- prologue: L1 gates(0) + cell -> h1(0) ----
    l1_gates(W1s, h1cur, gq1, *(const u64x2*)xin, C, kq, p, k2L1);
    __syncthreads();
    if (tid < Gdim) cell_up(gq1, h1nxt, c1, cj, cb);
    __syncthreads();
    { float4* t_ = h1cur; h1cur = h1nxt; h1nxt = t_; }   // h1cur = h1(0)

    // ---- teacher fused loop: t = 0..998, 2 barriers per step ----
    for (int t = 0; t < T_IN - 1; ++t) {
        // Phase G: L2 gates(t) + L1 gates(t+1) + proj y(t-1)
        l2_gates((kq < 2) ? h1cur : h2prv, l2, gq2, bb2_0, bb2_1, kq, p, k2L2);
        l1_gates(W1s, h1cur, gq1, *(const u64x2*)(xin + t + 1), C, kq, p, k2L1);
        if (tid < 128 && t >= 1)
            proj_y(h2prv, wlin, blin_r, ysv, out, b0, t - 1, tid);
        __syncthreads();
        // Phase C: both cell updates
        if (tid < Gdim) {
            cell_up(gq2, h2cur, c2, cj, cb);
            cell_up(gq1, h1nxt, c1, cj, cb);
        }
        __syncthreads();
        { float4* t_ = h1cur; h1cur = h1nxt; h1nxt = t_; }
        { float4* t_ = h2prv; h2prv = h2cur; h2cur = t_; }
    }
    // state: h1cur=h1(999), h2prv=h2(998); y written through 997

    // ---- drain: L2(999) + y(998); cell; y(999) ----
    l2_gates((kq < 2) ? h1cur : h2prv, l2, gq2, bb2_0, bb2_1, kq, p, k2L2);
    if (tid < 128)
        proj_y(h2prv, wlin, blin_r, ysv, out, b0, T_IN - 2, tid);
    __syncthreads();
    if (tid < Gdim) cell_up(gq2, h2cur, c2, cj, cb);
    __syncthreads();
    { float4* t_ = h2prv; h2prv = h2cur; h2cur = t_; }   // h2prv = h2(999)
    if (tid < 128)
        proj_y(h2prv, wlin, blin_r, ysv, out, b0, T_IN - 1, tid);
    __syncthreads();                                      // ysv = y(999)

    // ---- autoregressive serial phase: t = 1000..1299 ----
    for (int t = T_IN; t < T_TOT; ++t) {
        l1_gates(W1s, h1cur, gq1, *(const u64x2*)ysv, C, kq, p, k2L1);
        __syncthreads();
        if (tid < Gdim) cell_up(gq1, h1nxt, c1, cj, cb);
        __syncthreads();
        { float4* t_ = h1cur; h1cur = h1nxt; h1nxt = t_; }   // h1cur = h1(t)
        l2_gates((kq < 2) ? h1cur : h2prv, l2, gq2, bb2_0, bb2_1, kq, p, k2L2);
        __syncthreads();
        if (tid < Gdim) cell_up(gq2, h2cur, c2, cj, cb);
        __syncthreads();
        { float4* t_ = h2prv; h2prv = h2cur; h2cur = t_; }   // h2prv = h2(t)
        if (tid < 128)
            proj_y(h2prv, wlin, blin_r, ysv, out, b0, t, tid);
        __syncthreads();
    }
}

extern "C" void kernel_launch(void* const* d_in, const int* in_sizes, int n_in,
                              void* d_out, int out_size) {
    const float* input = (const float*)d_in[0];
    const float* W_ih1 = (const float*)d_in[1];
    const float* W_hh1 = (const float*)d_in[2];
    const float* b_ih1 = (const float*)d_in[3];
    const float* b_hh1 = (const float*)d_in[4];
    const float* W_ih2 = (const float*)d_in[5];
    const float* W_hh2 = (const float*)d_in[6];
    const float* b_ih2 = (const float*)d_in[7];
    const float* b_hh2 = (const float*)d_in[8];
    const float* W_lin = (const float*)d_in[9];
    const float* b_lin = (const float*)d_in[10];
    float* out = (float*)d_out;

    prep_weights<<<(100 * 200 + 255) / 256, 256>>>(W_hh1, W_ih2, W_hh2);

    const int smem_bytes = 39336 * (int)sizeof(float);
    cudaFuncSetAttribute(lstm2_kernel,
                         cudaFuncAttributeMaxDynamicSharedMemorySize, smem_bytes);
    lstm2_kernel<<<NCTA, NTHR, smem_bytes>>>(input, W_ih1, b_ih1, b_hh1,
                                             b_ih2, b_hh2, W_lin, b_lin, out);
}

// round 15
// speedup vs baseline: 1.0341x; 1.0341x over previous
#include <cuda_runtime.h>
#include <cuda_fp16.h>

#define Hdim  100
#define Gdim  400
#define T_IN  1000
#define T_TOT 1300
#define NB    4
#define NCTA  128
#define NTHR  800

// Gate-pair packed fp16 weights: [k2][p] -> uint2{ half2(gate p, k=2k2,2k2+1),
//                                                  half2(gate p+200, same k) }
__device__ uint2 g_W1P2[52 * 200];    // W_hh1, zero-padded k2 in {50,51}
__device__ uint2 g_W2P2[100 * 200];   // [W_ih2; W_hh2] over k<200

__global__ void prep_weights(const float* __restrict__ W_hh1,
                             const float* __restrict__ W_ih2,
                             const float* __restrict__ W_hh2) {
    int i = blockIdx.x * blockDim.x + threadIdx.x;
    if (i < 52 * 200) {
        int k2 = i / 200, p = i % 200, k = 2 * k2;
        uint2 u;
        if (k2 < 50) {
            __half2 a = __floats2half2_rn(W_hh1[p*Hdim + k],       W_hh1[p*Hdim + k + 1]);
            __half2 b = __floats2half2_rn(W_hh1[(p+200)*Hdim + k], W_hh1[(p+200)*Hdim + k + 1]);
            u.x = *reinterpret_cast<unsigned*>(&a);
            u.y = *reinterpret_cast<unsigned*>(&b);
        } else { u.x = 0u; u.y = 0u; }
        g_W1P2[i] = u;
    }
    if (i < 100 * 200) {
        int k2 = i / 200, p = i % 200, k = 2 * k2;
        const float* s0 = (k < Hdim) ? (W_ih2 + p*Hdim + k)       : (W_hh2 + p*Hdim + k - Hdim);
        const float* s1 = (k < Hdim) ? (W_ih2 + (p+200)*Hdim + k) : (W_hh2 + (p+200)*Hdim + k - Hdim);
        __half2 a = __floats2half2_rn(s0[0], s0[1]);
        __half2 b = __floats2half2_rn(s1[0], s1[1]);
        uint2 u;
        u.x = *reinterpret_cast<unsigned*>(&a);
        u.y = *reinterpret_cast<unsigned*>(&b);
        g_W2P2[i] = u;
    }
}

typedef unsigned long long u64;
typedef ulonglong2 u64x2;

__device__ __forceinline__ u64 pack2(float v) {
    u64 r; asm("mov.b64 %0, {%1, %1};" : "=l"(r) : "f"(v)); return r;
}
__device__ __forceinline__ void fma2(u64& a, u64 w, u64 h) {
    asm("fma.rn.f32x2 %0, %1, %2, %0;" : "+l"(a) : "l"(w), "l"(h));
}
__device__ __forceinline__ float tanhfast(float x) {
    float y; asm("tanh.approx.f32 %0, %1;" : "=f"(y) : "f"(x)); return y;
}
__device__ __forceinline__ float sigfast(float x) {
    return fmaf(0.5f, tanhfast(0.5f * x), 0.5f);
}

__global__ __launch_bounds__(NTHR, 1)
void lstm2_kernel(const float* __restrict__ input,
                  const float* __restrict__ W_ih1,
                  const float* __restrict__ b_ih1,
                  const float* __restrict__ b_hh1,
                  const float* __restrict__ b_ih2,
                  const float* __restrict__ b_hh2,
                  const float* __restrict__ W_lin,
                  const float* __restrict__ b_lin,
                  float* __restrict__ out)
{
    extern __shared__ float sm[];
    uint2*  W1s  = (uint2*)sm;                    // [52*200]  (20800 f)
    uint2*  W2s  = (uint2*)(sm + 20800);          // [48*200]  (19200 f): per quarter,
                                                  //  k2 = kq*25+13 .. kq*25+24
    float4* hcat = (float4*)(sm + 40000);         // [200] (h1|h2) x 4 batches (800 f)
    u64x2*  gq   = (u64x2*)(sm + 40800);          // [4][400] quarter partials (6400 f)
    float4* xin  = (float4*)(sm + 47200);         // [1000] input t-major (4000 f)
    float4* ysv  = (float4*)(sm + 51200);         // [1]
    float*  wlin = sm + 51204;                    // [100]
    // total 51304 floats = 205216 B

    const int tid = threadIdx.x;
    const int b0  = blockIdx.x * NB;
    const int kq  = tid / 200;       // k-quarter 0..3
    const int p   = tid % 200;       // gate-pair: gates p and p+200

    // ---- one-time init ----
    for (int i = tid; i < 52 * 200 * 2; i += NTHR)
        ((unsigned*)W1s)[i] = ((const unsigned*)g_W1P2)[i];
    // W2 smem subset: for quarter q, j<12: W2s[(q*12+j)*200+p] = g_W2P2[(q*25+13+j)*200+p]
    for (int i = tid; i < 48 * 200; i += NTHR) {
        int kqj = i / 200, pp = i % 200;
        int q = kqj / 12, j = kqj % 12;
        W2s[i] = g_W2P2[(q * 25 + 13 + j) * 200 + pp];
    }
    for (int i = tid; i < NB * T_IN; i += NTHR) {
        int t = i >> 2, b = i & 3;
        ((float*)xin)[i] = input[(b0 + b) * T_IN + t];
    }
    if (tid < Hdim) wlin[tid] = W_lin[tid];
    for (int i = tid; i < 200 * 4; i += NTHR) ((float*)hcat)[i] = 0.f;
    const float blin_r = __ldg(b_lin);

    // bias/x-weight constants, applied by quarter 0 only
    u64 bb1_0 = 0, bb1_1 = 0, wi_0 = 0, wi_1 = 0, bb2_0 = 0, bb2_1 = 0;
    if (kq == 0) {
        bb1_0 = pack2(b_ih1[p]       + b_hh1[p]);
        bb1_1 = pack2(b_ih1[p + 200] + b_hh1[p + 200]);
        wi_0  = pack2(W_ih1[p]);
        wi_1  = pack2(W_ih1[p + 200]);
        bb2_0 = pack2(b_ih2[p]       + b_hh2[p]);
        bb2_1 = pack2(b_ih2[p + 200] + b_hh2[p + 200]);
    }
    const int k2L1 = kq * 13;        // L1 k-pair range [k2L1, k2L1+13), padded to 52
    const int k2L2 = kq * 25;        // L2 k-pair range [k2L2, k2L2+25)

    const int cj = tid >> 2;         // cell role (tid < 400)
    const int cb = tid & 3;
    float c1 = 0.f, c2 = 0.f;
    __syncthreads();

    for (int t = 0; t < T_TOT; ++t) {
        // ---- Layer 1 gate partials: 2 gates/thread, fp16 W1 from smem ----
        {
            const u64x2 xp = (t < T_IN) ? *(const u64x2*)(xin + t)
                                        : *(const u64x2*)ysv;
            u64 a00 = bb1_0, a01 = bb1_0, a10 = bb1_1, a11 = bb1_1;
            if (kq == 0) {
                fma2(a00, wi_0, xp.x); fma2(a01, wi_0, xp.y);
                fma2(a10, wi_1, xp.x); fma2(a11, wi_1, xp.y);
            }
            const uint2* wp = W1s + p;
            #pragma unroll 13
            for (int k2 = k2L1; k2 < k2L1 + 13; ++k2) {
                const uint2 wu = wp[k2 * 200];                   // LDS.64
                const float2 wA = __half22float2(*reinterpret_cast<const __half2*>(&wu.x));
                const float2 wB = __half22float2(*reinterpret_cast<const __half2*>(&wu.y));
                const u64x2 h0 = *(const u64x2*)(hcat + 2*k2);   // broadcast
                const u64x2 h1 = *(const u64x2*)(hcat + 2*k2 + 1);
                const u64 wA0 = pack2(wA.x), wA1 = pack2(wA.y);
                const u64 wB0 = pack2(wB.x), wB1 = pack2(wB.y);
                fma2(a00, wA0, h0.x); fma2(a01, wA0, h0.y);
                fma2(a00, wA1, h1.x); fma2(a01, wA1, h1.y);
                fma2(a10, wB0, h0.x); fma2(a11, wB0, h0.y);
                fma2(a10, wB1, h1.x); fma2(a11, wB1, h1.y);
            }
            u64x2 r0; r0.x = a00; r0.y = a01;
            u64x2 r1; r1.x = a10; r1.y = a11;
            gq[kq * 400 + p]       = r0;
            gq[kq * 400 + p + 200] = r1;
        }
        __syncthreads();                                  // #1 gates ready

        // ---- Layer 1 cell update (sum 4 quarter partials) ----
        if (tid < Gdim) {
            const float* G = (const float*)gq;
            float vi = 0.f, vf = 0.f, vg = 0.f, vo = 0.f;
            #pragma unroll
            for (int q = 0; q < 4; ++q) {
                vi += G[(q*400 +       cj)*4 + cb];
                vf += G[(q*400 + 100 + cj)*4 + cb];
                vg += G[(q*400 + 200 + cj)*4 + cb];
                vo += G[(q*400 + 300 + cj)*4 + cb];
            }
            c1 = fmaf(sigfast(vf), c1, sigfast(vi) * tanhfast(vg));
            ((float*)hcat)[cj*4 + cb] = sigfast(vo) * tanhfast(c1);
        }
        __syncthreads();                                  // #2 h1(t) ready

        // ---- Layer 2 gate partials: 13 k-pairs via LDG + 12 k-pairs from smem ----
        {
            u64 a00 = bb2_0, a01 = bb2_0, a10 = bb2_1, a11 = bb2_1;
            const uint2* wpg = g_W2P2 + p;
            #pragma unroll 13
            for (int i = 0; i < 13; ++i) {
                const int k2 = k2L2 + i;
                const uint2 wu = __ldg(wpg + k2 * 200);          // LDG.64
                const float2 wA = __half22float2(*reinterpret_cast<const __half2*>(&wu.x));
                const float2 wB = __half22float2(*reinterpret_cast<const __half2*>(&wu.y));
                const u64x2 h0 = *(const u64x2*)(hcat + 2*k2);
                const u64x2 h1 = *(const u64x2*)(hcat + 2*k2 + 1);
                const u64 wA0 = pack2(wA.x), wA1 = pack2(wA.y);
                const u64 wB0 = pack2(wB.x), wB1 = pack2(wB.y);
                fma2(a00, wA0, h0.x); fma2(a01, wA0, h0.y);
                fma2(a00, wA1, h1.x); fma2(a01, wA1, h1.y);
                fma2(a10, wB0, h0.x); fma2(a11, wB0, h0.y);
                fma2(a10, wB1, h1.x); fma2(a11, wB1, h1.y);
            }
            const uint2* wps = W2s + kq * 12 * 200 + p;
            #pragma unroll 12
            for (int j = 0; j < 12; ++j) {
                const int k2 = k2L2 + 13 + j;
                const uint2 wu = wps[j * 200];                   // LDS.64
                const float2 wA = __half22float2(*reinterpret_cast<const __half2*>(&wu.x));
                const float2 wB = __half22float2(*reinterpret_cast<const __half2*>(&wu.y));
                const u64x2 h0 = *(const u64x2*)(hcat + 2*k2);
                const u64x2 h1 = *(const u64x2*)(hcat + 2*k2 + 1);
                const u64 wA0 = pack2(wA.x), wA1 = pack2(wA.y);
                const u64 wB0 = pack2(wB.x), wB1 = pack2(wB.y);
                fma2(a00, wA0, h0.x); fma2(a01, wA0, h0.y);
                fma2(a00, wA1, h1.x); fma2(a01, wA1, h1.y);
                fma2(a10, wB0, h0.x); fma2(a11, wB0, h0.y);
                fma2(a10, wB1, h1.x); fma2(a11, wB1, h1.y);
            }
            u64x2 r0; r0.x = a00; r0.y = a01;
            u64x2 r1; r1.x = a10; r1.y = a11;
            gq[kq * 400 + p]       = r0;
            gq[kq * 400 + p + 200] = r1;
        }
        __syncthreads();                                  // #3 gates ready

        // ---- Layer 2 cell update ----
        if (tid < Gdim) {
            const float* G = (const float*)gq;
            float vi = 0.f, vf = 0.f, vg = 0.f, vo = 0.f;
            #pragma unroll
            for (int q = 0; q < 4; ++q) {
                vi += G[(q*400 +       cj)*4 + cb];
                vf += G[(q*400 + 100 + cj)*4 + cb];
                vg += G[(q*400 + 200 + cj)*4 + cb];
                vo += G[(q*400 + 300 + cj)*4 + cb];
            }
            c2 = fmaf(sigfast(vf), c2, sigfast(vi) * tanhfast(vg));
            ((float*)hcat)[(Hdim + cj)*4 + cb] = sigfast(vo) * tanhfast(c2);
        }
        __syncthreads();                                  // #4 h2(t) ready

        // ---- Output projection (warps 0-3); overlaps next L1 in teacher phase ----
        if (tid < 128) {
            const int w = tid >> 5, l = tid & 31;
            float s = 0.f;
            #pragma unroll
            for (int j = 0; j < Hdim; j += 32) {
                const int jj = j + l;
                if (jj < Hdim)
                    s = fmaf(((const float*)hcat)[(Hdim + jj)*4 + w], wlin[jj], s);
            }
            #pragma unroll
            for (int o = 16; o > 0; o >>= 1)
                s += __shfl_down_sync(0xffffffffu, s, o);
            if (l == 0) {
                const float y = s + blin_r;
                out[(b0 + w) * T_TOT + t] = y;
                ((float*)ysv)[w] = y;
            }
        }
        // ysv only feeds x when t+1 >= T_IN; otherwise let warps run ahead.
        if (t >= T_IN - 1) __syncthreads();
    }
}

extern "C" void kernel_launch(void* const* d_in, const int* in_sizes, int n_in,
                              void* d_out, int out_size) {
    const float* input = (const float*)d_in[0];
    const float* W_ih1 = (const float*)d_in[1];
    const float* W_hh1 = (const float*)d_in[2];
    const float* b_ih1 = (const float*)d_in[3];
    const float* b_hh1 = (const float*)d_in[4];
    const float* W_ih2 = (const float*)d_in[5];
    const float* W_hh2 = (const float*)d_in[6];
    const float* b_ih2 = (const float*)d_in[7];
    const float* b_hh2 = (const float*)d_in[8];
    const float* W_lin = (const float*)d_in[9];
    const float* b_lin = (const float*)d_in[10];
    float* out = (float*)d_out;

    prep_weights<<<(100 * 200 + 255) / 256, 256>>>(W_hh1, W_ih2, W_hh2);

    const int smem_bytes = 51304 * (int)sizeof(float);
    cudaFuncSetAttribute(lstm2_kernel,
                         cudaFuncAttributeMaxDynamicSharedMemorySize, smem_bytes);
    lstm2_kernel<<<NCTA, NTHR, smem_bytes>>>(input, W_ih1, b_ih1, b_hh1,
                                             b_ih2, b_hh2, W_lin, b_lin, out);
}

// round 16
// speedup vs baseline: 2.2586x; 2.1842x over previous
#include <cuda_runtime.h>
#include <cuda_fp16.h>

#define Hdim  100
#define T_IN  1000
#define T_TOT 1300
#define NB    4
#define NCTA  128
#define NTHR  800          // 25 warps x 16 gates = 400 gates
#define NW    25
#define KS1   7            // K1 = 112 = 7 k-steps of 16
#define KS2   13           // K2 = 208 = 13 k-steps of 16

// Fragment-prepacked A matrices for mma.m16n8k16 (row.col, f16):
//   A1[g][k]: k=0 -> W_ih1[g]; k=1 -> b1[g]; k in [2,102) -> W_hh1[g][k-2]; else 0
//   A2[g][k]: k=0 -> b2[g];    k in [1,101) -> W_ih2[g][k-1];
//             k in [101,201) -> W_hh2[g][k-101]; else 0
// Layout: [warp][kstep][lane] -> uint4 {a0,a1,a2,a3} per the PTX fragment map.
__device__ uint4 g_A1pk[NW * KS1 * 32];   // 5600 * 16B  (copied to smem)
__device__ uint4 g_A2pk[NW * KS2 * 32];   // 10400 * 16B (streamed via LDG)

__device__ __forceinline__ float a1_elem(const float* W_ih1, const float* W_hh1,
                                         const float* b_ih1, const float* b_hh1,
                                         int r, int k) {
    if (k == 0) return W_ih1[r];
    if (k == 1) return b_ih1[r] + b_hh1[r];
    if (k < 102) return W_hh1[r * Hdim + (k - 2)];
    return 0.f;
}
__device__ __forceinline__ float a2_elem(const float* W_ih2, const float* W_hh2,
                                         const float* b_ih2, const float* b_hh2,
                                         int r, int k) {
    if (k == 0) return b_ih2[r] + b_hh2[r];
    if (k < 101)  return W_ih2[r * Hdim + (k - 1)];
    if (k < 201)  return W_hh2[r * Hdim + (k - 101)];
    return 0.f;
}

__global__ void prep_weights(const float* __restrict__ W_ih1,
                             const float* __restrict__ W_hh1,
                             const float* __restrict__ b_ih1,
                             const float* __restrict__ b_hh1,
                             const float* __restrict__ W_ih2,
                             const float* __restrict__ W_hh2,
                             const float* __restrict__ b_ih2,
                             const float* __restrict__ b_hh2) {
    int i = blockIdx.x * blockDim.x + threadIdx.x;
    if (i < NW * KS1 * 32) {
        int w = i / (KS1 * 32), s = (i % (KS1 * 32)) / 32, lane = i % 32;
        int g = lane >> 2, m = lane & 3;
        int r0 = w * 16 + g, r1 = r0 + 8, c0 = s * 16 + 2 * m;
        __half2 h;
        uint4 u;
        h = __floats2half2_rn(a1_elem(W_ih1,W_hh1,b_ih1,b_hh1, r0, c0),
                              a1_elem(W_ih1,W_hh1,b_ih1,b_hh1, r0, c0+1));
        u.x = *reinterpret_cast<unsigned*>(&h);
        h = __floats2half2_rn(a1_elem(W_ih1,W_hh1,b_ih1,b_hh1, r1, c0),
                              a1_elem(W_ih1,W_hh1,b_ih1,b_hh1, r1, c0+1));
        u.y = *reinterpret_cast<unsigned*>(&h);
        h = __floats2half2_rn(a1_elem(W_ih1,W_hh1,b_ih1,b_hh1, r0, c0+8),
                              a1_elem(W_ih1,W_hh1,b_ih1,b_hh1, r0, c0+9));
        u.z = *reinterpret_cast<unsigned*>(&h);
        h = __floats2half2_rn(a1_elem(W_ih1,W_hh1,b_ih1,b_hh1, r1, c0+8),
                              a1_elem(W_ih1,W_hh1,b_ih1,b_hh1, r1, c0+9));
        u.w = *reinterpret_cast<unsigned*>(&h);
        g_A1pk[i] = u;
    }
    if (i < NW * KS2 * 32) {
        int w = i / (KS2 * 32), s = (i % (KS2 * 32)) / 32, lane = i % 32;
        int g = lane >> 2, m = lane & 3;
        int r0 = w * 16 + g, r1 = r0 + 8, c0 = s * 16 + 2 * m;
        __half2 h;
        uint4 u;
        h = __floats2half2_rn(a2_elem(W_ih2,W_hh2,b_ih2,b_hh2, r0, c0),
                              a2_elem(W_ih2,W_hh2,b_ih2,b_hh2, r0, c0+1));
        u.x = *reinterpret_cast<unsigned*>(&h);
        h = __floats2half2_rn(a2_elem(W_ih2,W_hh2,b_ih2,b_hh2, r1, c0),
                              a2_elem(W_ih2,W_hh2,b_ih2,b_hh2, r1, c0+1));
        u.y = *reinterpret_cast<unsigned*>(&h);
        h = __floats2half2_rn(a2_elem(W_ih2,W_hh2,b_ih2,b_hh2, r0, c0+8),
                              a2_elem(W_ih2,W_hh2,b_ih2,b_hh2, r0, c0+9));
        u.z = *reinterpret_cast<unsigned*>(&h);
        h = __floats2half2_rn(a2_elem(W_ih2,W_hh2,b_ih2,b_hh2, r1, c0+8),
                              a2_elem(W_ih2,W_hh2,b_ih2,b_hh2, r1, c0+9));
        u.w = *reinterpret_cast<unsigned*>(&h);
        g_A2pk[i] = u;
    }
}

__device__ __forceinline__ void mma16816(float& d0, float& d1, float& d2, float& d3,
                                         uint4 A, uint2 B) {
    asm volatile(
        "mma.sync.aligned.m16n8k16.row.col.f32.f16.f16.f32 "
        "{%0,%1,%2,%3}, {%4,%5,%6,%7}, {%8,%9}, {%0,%1,%2,%3};"
        : "+f"(d0), "+f"(d1), "+f"(d2), "+f"(d3)
        : "r"(A.x), "r"(A.y), "r"(A.z), "r"(A.w), "r"(B.x), "r"(B.y));
}

__device__ __forceinline__ float tanhfast(float x) {
    float y; asm("tanh.approx.f32 %0, %1;" : "=f"(y) : "f"(x)); return y;
}
__device__ __forceinline__ float sigfast(float x) {
    return fmaf(0.5f, tanhfast(0.5f * x), 0.5f);
}

// B fragment scatter-write: element (k, n) of B lives at one half position.
//   s = k/16, r = k%16, lane = n*4 + (r%8)/2, word = r/8, halfsel = r%2
__device__ __forceinline__ void bf_write(__half* BF, int k, int n, __half v) {
    int s = k >> 4, r = k & 15;
    int lane = n * 4 + ((r & 7) >> 1);
    BF[(s * 32 + lane) * 4 + (r >> 3) * 2 + (r & 1)] = v;
}

__global__ __launch_bounds__(NTHR, 1)
void lstm2_kernel(const float* __restrict__ input,
                  const float* __restrict__ W_lin,
                  const float* __restrict__ b_lin,
                  float* __restrict__ out)
{
    extern __shared__ float sm[];
    uint4*  A1s  = (uint4*)sm;                 // [5600]  f[0..22400)
    uint2*  BF1  = (uint2*)(sm + 22400);       // [224]   f[22400..22848)
    uint2*  BF2  = (uint2*)(sm + 22848);       // [416]   f[22848..23680)
    float*  gq   = sm + 23680;                 // [1600]  gate exchange
    float*  h2f  = sm + 25280;                 // [400]   h2 fp32 for proj
    float*  xin  = sm + 25680;                 // [4000]  input t-major
    float*  ysv  = sm + 29680;                 // [4]
    float*  wlin = sm + 29684;                 // [100]
    // total 29784 floats = 119136 B

    __half* BF1h = (__half*)BF1;
    __half* BF2h = (__half*)BF2;

    const int tid  = threadIdx.x;
    const int w    = tid >> 5;
    const int lane = tid & 31;
    const int g    = lane >> 2;
    const int m    = lane & 3;
    const int b0   = blockIdx.x * NB;

    // ---- one-time init ----
    for (int i = tid; i < NW * KS1 * 32 * 4; i += NTHR)
        ((unsigned*)A1s)[i] = ((const unsigned*)g_A1pk)[i];
    for (int i = tid; i < 224 * 2; i += NTHR) ((unsigned*)BF1)[i] = 0u;  // zero (pads!)
    for (int i = tid; i < 416 * 2; i += NTHR) ((unsigned*)BF2)[i] = 0u;
    for (int i = tid; i < NB * T_IN; i += NTHR) {
        int t = i >> 2, b = i & 3;
        xin[i] = input[(b0 + b) * T_IN + t];
    }
    if (tid < Hdim) wlin[tid] = W_lin[tid];
    const float blin_r = __ldg(b_lin);
    __syncthreads();
    if (tid < NB) {
        bf_write(BF1h, 1, tid, __float2half_rn(1.0f));          // const-1 row (bias)
        bf_write(BF2h, 0, tid, __float2half_rn(1.0f));
        bf_write(BF1h, 0, tid, __float2half_rn(xin[tid]));      // x(0)
    }
    const int cj = tid >> 2, cb = tid & 3;   // cell role (tid < 400)
    float c1 = 0.f, c2 = 0.f;
    __syncthreads();

    const uint4* a1p = A1s + w * (KS1 * 32) + lane;
    const uint4* a2p = g_A2pk + w * (KS2 * 32) + lane;
    const uint2* b1p = BF1 + lane;
    const uint2* b2p = BF2 + lane;
    const int gate0 = w * 16 + g;
    const bool stl  = (m < 2);               // lanes holding real batch columns

    for (int t = 0; t < T_TOT; ++t) {
        // ======== Layer 1: D1[400x8] = A1[400x112] * B1[112x8] ========
        {
            float d0 = 0.f, d1 = 0.f, d2 = 0.f, d3 = 0.f;
            #pragma unroll
            for (int s = 0; s < KS1; ++s)
                mma16816(d0, d1, d2, d3, a1p[s * 32], b1p[s * 32]);
            if (stl) {
                *(float2*)(gq + (gate0    ) * 4 + 2 * m) = make_float2(d0, d1);
                *(float2*)(gq + (gate0 + 8) * 4 + 2 * m) = make_float2(d2, d3);
            }
        }
        __syncthreads();                                  // #1 gates ready

        // ---- Layer 1 cell (tid < 400): c1 in regs, h1 -> BF1(k=2+cj), BF2(k=1+cj)
        if (tid < 400) {
            const float vi = gq[(      cj) * 4 + cb];
            const float vf = gq[(100 + cj) * 4 + cb];
            const float vg = gq[(200 + cj) * 4 + cb];
            const float vo = gq[(300 + cj) * 4 + cb];
            c1 = fmaf(sigfast(vf), c1, sigfast(vi) * tanhfast(vg));
            const __half hh = __float2half_rn(sigfast(vo) * tanhfast(c1));
            bf_write(BF1h, 2 + cj, cb, hh);
            bf_write(BF2h, 1 + cj, cb, hh);
        }
        __syncthreads();                                  // #2 h1(t) ready

        // ======== Layer 2: D2[400x8] = A2[400x208] * B2[208x8] ========
        {
            float d0 = 0.f, d1 = 0.f, d2 = 0.f, d3 = 0.f;
            #pragma unroll
            for (int s = 0; s < KS2; ++s)
                mma16816(d0, d1, d2, d3, __ldg(a2p + s * 32), b2p[s * 32]);
            if (stl) {
                *(float2*)(gq + (gate0    ) * 4 + 2 * m) = make_float2(d0, d1);
                *(float2*)(gq + (gate0 + 8) * 4 + 2 * m) = make_float2(d2, d3);
            }
        }
        __syncthreads();                                  // #3 gates ready

        // ---- Layer 2 cell: h2 -> BF2(k=101+cj) fp16 + h2f fp32; x(t+1) teacher ----
        if (tid < 400) {
            const float vi = gq[(      cj) * 4 + cb];
            const float vf = gq[(100 + cj) * 4 + cb];
            const float vg = gq[(200 + cj) * 4 + cb];
            const float vo = gq[(300 + cj) * 4 + cb];
            c2 = fmaf(sigfast(vf), c2, sigfast(vi) * tanhfast(vg));
            const float h2v = sigfast(vo) * tanhfast(c2);
            bf_write(BF2h, 101 + cj, cb, __float2half_rn(h2v));
            h2f[cj * 4 + cb] = h2v;
        }
        if (tid < NB && t + 1 < T_IN)
            bf_write(BF1h, 0, tid, __float2half_rn(xin[(t + 1) * 4 + tid]));
        __syncthreads();                                  // #4 h2(t) ready

        // ---- Output projection (warps 0-3); overlaps next L1 in teacher phase ----
        if (tid < 128) {
            const int wb = tid >> 5, l = tid & 31;
            float s = 0.f;
            #pragma unroll
            for (int j0 = 0; j0 < Hdim; j0 += 32) {
                const int j = j0 + l;
                if (j < Hdim) s = fmaf(h2f[j * 4 + wb], wlin[j], s);
            }
            #pragma unroll
            for (int o = 16; o > 0; o >>= 1)
                s += __shfl_down_sync(0xffffffffu, s, o);
            if (l == 0) {
                const float y = s + blin_r;
                out[(b0 + wb) * T_TOT + t] = y;
                ysv[wb] = y;
            }
        }
        // Autoregressive feedback: x(t+1) = y(t) needs proj done + visible.
        if (t >= T_IN - 1 && t + 1 < T_TOT) {
            __syncthreads();
            if (tid < NB) bf_write(BF1h, 0, tid, __float2half_rn(ysv[tid]));
            __syncthreads();
        }
    }
}

extern "C" void kernel_launch(void* const* d_in, const int* in_sizes, int n_in,
                              void* d_out, int out_size) {
    const float* input = (const float*)d_in[0];
    const float* W_ih1 = (const float*)d_in[1];
    const float* W_hh1 = (const float*)d_in[2];
    const float* b_ih1 = (const float*)d_in[3];
    const float* b_hh1 = (const float*)d_in[4];
    const float* W_ih2 = (const float*)d_in[5];
    const float* W_hh2 = (const float*)d_in[6];
    const float* b_ih2 = (const float*)d_in[7];
    const float* b_hh2 = (const float*)d_in[8];
    const float* W_lin = (const float*)d_in[9];
    const float* b_lin = (const float*)d_in[10];
    float* out = (float*)d_out;

    prep_weights<<<(NW * KS2 * 32 + 255) / 256, 256>>>(W_ih1, W_hh1, b_ih1, b_hh1,
                                                       W_ih2, W_hh2, b_ih2, b_hh2);

    const int smem_bytes = 29784 * (int)sizeof(float);
    cudaFuncSetAttribute(lstm2_kernel,
                         cudaFuncAttributeMaxDynamicSharedMemorySize, smem_bytes);
    lstm2_kernel<<<NCTA, NTHR, smem_bytes>>>(input, W_lin, b_lin, out);
}